// round 14
// baseline (speedup 1.0000x reference)
#include <cuda_runtime.h>

#define T_STEPS 1000
#define C_CH    3
#define H_DIM   64
#define W_DIM   64
#define HW      (H_DIM * W_DIM)       // 4096
#define HW4     (HW / 4)              // 1024
#define PIX     (C_CH * HW)           // 12288
#define PIX4    (PIX / 4)             // 3072
#define NSEG    100
#define SEGLEN  (T_STEPS / NSEG)      // 10
#define NCHUNK  (PIX4 / 256)          // 12
#define TILE_ROWS 16

__device__ float g_E[(size_t)T_STEPS * PIX];      // ~49 MB scratch
__device__ float g_Part[NSEG * PIX];              // per-(segment,pixel) partial sums
__device__ int   g_flag[NSEG * NCHUNK];           // publish flags (epoch-tagged), zero-init
__device__ int   g_epoch = 0;
__constant__ float c_w[81];                       // conv weights (LDCU port)

__device__ __forceinline__ int ld_acquire(const int* p) {
    int v;
    asm volatile("ld.acquire.gpu.b32 %0, [%1];" : "=r"(v) : "l"(p) : "memory");
    return v;
}
__device__ __forceinline__ void st_release(int* p, int v) {
    asm volatile("st.release.gpu.b32 [%0], %1;" :: "l"(p), "r"(v) : "memory");
}

__global__ void epoch_kernel() { if (threadIdx.x == 0) g_epoch += 1; }

// ---------------------------------------------------------------------------
// Kernel A (exact R7 body — proven 29.2us): 256 threads, one (16-row tile,
// image j). Thread = 1 row x 4 cols x 3 output channels (12 accumulators).
// Inputs via LDS.128; weights via the constant port; ec applied at the end.
// ---------------------------------------------------------------------------
__global__ __launch_bounds__(256, 4) void conv_kernel(
    const float* __restrict__ src,       // images 0..T-1, (.., C, H, W)
    const float* __restrict__ temb,      // (T, 3)
    const int*   __restrict__ t_arr,     // (T,)
    const float* __restrict__ et_coeff)  // (T,)
{
    __shared__ float4 s_in4[3][18][18];  // [ci][row][quad]; quad q = cols 4q-4..4q-1

    const int j   = blockIdx.y;
    const int r0  = blockIdx.x * TILE_ROWS;
    const int tid = threadIdx.x;
    const int h   = tid >> 4;            // row 0..15
    const int k   = tid & 15;            // col-group 0..15 (cols 4k..4k+3)

    const float4* img4 = (const float4*)(src + (size_t)j * PIX);
    for (int l = tid; l < 3 * 18 * 18; l += 256) {
        int ci  = l / 324;
        int rem = l - ci * 324;
        int r   = rem / 18;
        int q   = rem - r * 18;
        int gh  = r0 + r - 1;
        float4 v = make_float4(0.f, 0.f, 0.f, 0.f);
        if (q >= 1 && q <= 16 && gh >= 0 && gh < H_DIM)
            v = img4[ci * HW4 + gh * 16 + (q - 1)];
        (&s_in4[0][0][0])[l] = v;
    }
    __syncthreads();

    const int   trev = __ldg(t_arr + j);
    const float ec   = __ldg(et_coeff + j);

    float acc[3][4];
#pragma unroll
    for (int c = 0; c < 3; c++) {
        const float tb = __ldg(temb + trev * 3 + c);
#pragma unroll
        for (int s = 0; s < 4; s++) acc[c][s] = tb;
    }

#pragma unroll 1
    for (int ci = 0; ci < 3; ci++) {
        float v[3][6];
#pragma unroll
        for (int r = 0; r < 3; r++) {
            float4 A = s_in4[ci][h + r][k];
            float4 B = s_in4[ci][h + r][k + 1];
            float4 C = s_in4[ci][h + r][k + 2];
            v[r][0] = A.w; v[r][1] = B.x; v[r][2] = B.y;
            v[r][3] = B.z; v[r][4] = B.w; v[r][5] = C.x;
        }
#pragma unroll
        for (int dh = 0; dh < 3; dh++)
#pragma unroll
            for (int dw = 0; dw < 3; dw++) {
                const int tap = ci * 9 + dh * 3 + dw;
                const float w0 = c_w[tap];
                const float w1 = c_w[27 + tap];
                const float w2 = c_w[54 + tap];
#pragma unroll
                for (int s = 0; s < 4; s++) {
                    const float xv = v[dh][dw + s];
                    acc[0][s] = fmaf(w0, xv, acc[0][s]);
                    acc[1][s] = fmaf(w1, xv, acc[1][s]);
                    acc[2][s] = fmaf(w2, xv, acc[2][s]);
                }
            }
    }

    float4* Ej4 = (float4*)(g_E + (size_t)j * PIX);
    const int gq = (r0 + h) * 16 + k;
#pragma unroll
    for (int c = 0; c < 3; c++)
        Ej4[c * HW4 + gq] = make_float4(acc[c][0] * ec, acc[c][1] * ec,
                                        acc[c][2] * ec, acc[c][3] * ec);
}

// ---------------------------------------------------------------------------
// Kernel C: fused single-pass scan + combine with decoupled lookback.
// Block = (pixel-chunk x, segment s). E kept in registers (read once).
// Deterministic: every block sums ALL predecessor partials in order 0..s-1.
// ---------------------------------------------------------------------------
__global__ __launch_bounds__(256) void scan_fused_kernel(
    float*       __restrict__ dst,          // (T+1, C, H, W)
    const float* __restrict__ xT,           // first image of original x
    const float* __restrict__ alpha_ratio,  // (T,)
    const float* __restrict__ epc)          // (T,)
{
    const int s   = blockIdx.y;             // segment
    const int x   = blockIdx.x;             // chunk
    const int p4  = x * 256 + threadIdx.x;  // < PIX4
    const int epoch = g_epoch;              // constant during this launch

    // ---- pass 1: load segment E values into registers, local sum ----
    const int t0 = s * SEGLEN;
    float4 e[SEGLEN];
    float4 loc = make_float4(0.f, 0.f, 0.f, 0.f);
#pragma unroll
    for (int jj = 0; jj < SEGLEN; jj++) {
        e[jj] = __ldg((const float4*)g_E + (size_t)(t0 + jj) * PIX4 + p4);
        loc.x += e[jj].x; loc.y += e[jj].y; loc.z += e[jj].z; loc.w += e[jj].w;
    }

    // ---- publish partial ----
    ((float4*)g_Part)[s * PIX4 + p4] = loc;
    __threadfence();
    __syncthreads();
    if (threadIdx.x == 0)
        st_release(&g_flag[s * NCHUNK + x], epoch);

    // ---- lookback: sum ALL predecessor partials in fixed order ----
    float4 acc = make_float4(0.f, 0.f, 0.f, 0.f);
    for (int sp = 0; sp < s; sp++) {
        while (ld_acquire(&g_flag[sp * NCHUNK + x]) != epoch) { }
        const float4 ps = ((const float4*)g_Part)[sp * PIX4 + p4];
        acc.x += ps.x; acc.y += ps.y; acc.z += ps.z; acc.w += ps.w;
    }

    // ---- pass 2: emit outputs from registers ----
    const float4 xv = ((const float4*)xT)[p4];
    if (s == 0)
        ((float4*)dst)[p4] = xv;             // image 0 stays xT

#pragma unroll
    for (int jj = 0; jj < SEGLEN; jj++) {
        const int j = t0 + jj;
        acc.x += e[jj].x; acc.y += e[jj].y; acc.z += e[jj].z; acc.w += e[jj].w;
        const float ar = __ldg(alpha_ratio + j);
        const float ep = __ldg(epc + j);
        float4 o;
        o.x = fmaf(ar, xv.x, ep * acc.x);
        o.y = fmaf(ar, xv.y, ep * acc.y);
        o.z = fmaf(ar, xv.z, ep * acc.z);
        o.w = fmaf(ar, xv.w, ep * acc.w);
        ((float4*)dst)[(size_t)(j + 1) * PIX4 + p4] = o;
    }
}

extern "C" void kernel_launch(void* const* d_in, const int* in_sizes, int n_in,
                              void* d_out, int out_size)
{
    const float* x           = (const float*)d_in[0];  // (T+1, 3, 64, 64)
    const int*   t_arr       = (const int*)  d_in[1];  // (T,)
    const float* alpha_ratio = (const float*)d_in[2];  // (T,1,1,1)
    const float* et_coeff    = (const float*)d_in[3];  // (T,1,1,1)
    const float* epc         = (const float*)d_in[4];  // (T,1,1,1)
    const float* conv_w      = (const float*)d_in[5];  // (3,3,3,3)
    const float* temb        = (const float*)d_in[6];  // (T, 3)
    float*       out         = (float*)d_out;

    cudaMemcpyToSymbolAsync(c_w, conv_w, 81 * sizeof(float), 0,
                            cudaMemcpyDeviceToDevice);

    dim3 gA(H_DIM / TILE_ROWS, T_STEPS), bA(256);      // (4, 1000)
    dim3 gC(NCHUNK, NSEG),               bC(256);      // (12, 100)

    for (int it = 0; it < 3; it++) {
        const float* src = (it == 0) ? x : out;  // conv reads images 0..T-1
        conv_kernel<<<gA, bA>>>(src, temb, t_arr, et_coeff);
        epoch_kernel<<<1, 32>>>();
        scan_fused_kernel<<<gC, bC>>>(out, x, alpha_ratio, epc);
    }
}

// round 15
// speedup vs baseline: 2.5377x; 2.5377x over previous
#include <cuda_runtime.h>
#include <cuda_fp16.h>

#define T_STEPS 1000
#define C_CH    3
#define H_DIM   64
#define W_DIM   64
#define HW      (H_DIM * W_DIM)       // 4096
#define HW4     (HW / 4)              // 1024
#define PIX     (C_CH * HW)           // 12288
#define PIX4    (PIX / 4)             // 3072
#define NSEG    50
#define SEGLEN  (T_STEPS / NSEG)      // 20
#define TILE_ROWS 16

__device__ __half g_E[(size_t)T_STEPS * PIX];     // ~24.5 MB scratch (fp16)
__device__ float  g_Psum[NSEG * PIX];             // ~2.5 MB
__device__ float  g_Ppre[NSEG * PIX];             // exclusive prefix of g_Psum
__constant__ float c_w[81];                       // conv weights (LDCU port)

// ---------------------------------------------------------------------------
// Kernel A (proven R7 body, fp16 E stores): 256 threads, one (16-row tile,
// image j). Thread = 1 row x 4 cols x 3 output channels (12 accumulators).
// ---------------------------------------------------------------------------
__global__ __launch_bounds__(256, 4) void conv_kernel(
    const float* __restrict__ src,       // images 0..T-1, (.., C, H, W)
    const float* __restrict__ temb,      // (T, 3)
    const int*   __restrict__ t_arr,     // (T,)
    const float* __restrict__ et_coeff)  // (T,)
{
    __shared__ float4 s_in4[3][18][18];  // [ci][row][quad]; quad q = cols 4q-4..4q-1

    const int j   = blockIdx.y;
    const int r0  = blockIdx.x * TILE_ROWS;
    const int tid = threadIdx.x;
    const int h   = tid >> 4;            // row 0..15
    const int k   = tid & 15;            // col-group 0..15 (cols 4k..4k+3)

    const float4* img4 = (const float4*)(src + (size_t)j * PIX);
    for (int l = tid; l < 3 * 18 * 18; l += 256) {
        int ci  = l / 324;
        int rem = l - ci * 324;
        int r   = rem / 18;
        int q   = rem - r * 18;
        int gh  = r0 + r - 1;
        float4 v = make_float4(0.f, 0.f, 0.f, 0.f);
        if (q >= 1 && q <= 16 && gh >= 0 && gh < H_DIM)
            v = img4[ci * HW4 + gh * 16 + (q - 1)];
        (&s_in4[0][0][0])[l] = v;
    }
    __syncthreads();

    const int   trev = __ldg(t_arr + j);
    const float ec   = __ldg(et_coeff + j);

    float acc[3][4];
#pragma unroll
    for (int c = 0; c < 3; c++) {
        const float tb = __ldg(temb + trev * 3 + c);
#pragma unroll
        for (int s = 0; s < 4; s++) acc[c][s] = tb;
    }

#pragma unroll 1
    for (int ci = 0; ci < 3; ci++) {
        float v[3][6];
#pragma unroll
        for (int r = 0; r < 3; r++) {
            float4 A = s_in4[ci][h + r][k];
            float4 B = s_in4[ci][h + r][k + 1];
            float4 C = s_in4[ci][h + r][k + 2];
            v[r][0] = A.w; v[r][1] = B.x; v[r][2] = B.y;
            v[r][3] = B.z; v[r][4] = B.w; v[r][5] = C.x;
        }
#pragma unroll
        for (int dh = 0; dh < 3; dh++)
#pragma unroll
            for (int dw = 0; dw < 3; dw++) {
                const int tap = ci * 9 + dh * 3 + dw;
                const float w0 = c_w[tap];
                const float w1 = c_w[27 + tap];
                const float w2 = c_w[54 + tap];
#pragma unroll
                for (int s = 0; s < 4; s++) {
                    const float xv = v[dh][dw + s];
                    acc[0][s] = fmaf(w0, xv, acc[0][s]);
                    acc[1][s] = fmaf(w1, xv, acc[1][s]);
                    acc[2][s] = fmaf(w2, xv, acc[2][s]);
                }
            }
    }

    __half* Ej = g_E + (size_t)j * PIX;
    const int gq = (r0 + h) * 16 + k;            // float4-group index in channel plane
#pragma unroll
    for (int c = 0; c < 3; c++) {
        union { uint2 u; __half2 h[2]; } pk;
        pk.h[0] = __floats2half2_rn(acc[c][0] * ec, acc[c][1] * ec);
        pk.h[1] = __floats2half2_rn(acc[c][2] * ec, acc[c][3] * ec);
        *(uint2*)(Ej + c * HW + gq * 4) = pk.u;  // STG.64
    }
}

// ---------------------------------------------------------------------------
// Kernel B: per-segment partial sums of E (fp16 loads, fp32 accumulate).
// ---------------------------------------------------------------------------
__global__ __launch_bounds__(256) void psum_kernel()
{
    const int p4  = blockIdx.x * 256 + threadIdx.x;   // < PIX4
    const int seg = blockIdx.y;
    const __half* base = g_E + (size_t)seg * SEGLEN * PIX + p4 * 4;
    float4 s = make_float4(0.f, 0.f, 0.f, 0.f);
#pragma unroll 10
    for (int j = 0; j < SEGLEN; j++) {
        uint2 u = *(const uint2*)(base + (size_t)j * PIX);
        float2 f0 = __half22float2(*(const __half2*)&u.x);
        float2 f1 = __half22float2(*(const __half2*)&u.y);
        s.x += f0.x; s.y += f0.y; s.z += f1.x; s.w += f1.y;
    }
    ((float4*)g_Psum)[seg * PIX4 + p4] = s;
}

// ---------------------------------------------------------------------------
// Kernel B2: exclusive prefix of g_Psum along segments (per scalar pixel).
// ---------------------------------------------------------------------------
__global__ __launch_bounds__(256) void prefix_kernel()
{
    const int p = blockIdx.x * 256 + threadIdx.x;     // < PIX
    float run = 0.f;
#pragma unroll 10
    for (int s = 0; s < NSEG; s++) {
        const float v = g_Psum[s * PIX + p];
        g_Ppre[s * PIX + p] = run;
        run += v;
    }
}

// ---------------------------------------------------------------------------
// Kernel C: offset (one load) + local scan + combine (fp16 E, fp32 math).
// ---------------------------------------------------------------------------
__global__ __launch_bounds__(256) void scan_combine_kernel(
    float*       __restrict__ dst,          // (T+1, C, H, W)
    const float* __restrict__ xT,           // first image of original x
    const float* __restrict__ alpha_ratio,  // (T,)
    const float* __restrict__ epc)          // (T,)
{
    const int seg = blockIdx.y;
    const int p4  = blockIdx.x * 256 + threadIdx.x;   // < PIX4

    float4 acc = ((const float4*)g_Ppre)[seg * PIX4 + p4];

    const float4 xv = ((const float4*)xT)[p4];
    if (seg == 0)
        ((float4*)dst)[p4] = xv;             // image 0 stays xT

    const int t0 = seg * SEGLEN;
    const __half* base = g_E + (size_t)t0 * PIX + p4 * 4;
#pragma unroll 10
    for (int jj = 0; jj < SEGLEN; jj++) {
        const int j = t0 + jj;
        uint2 u = __ldcs((const uint2*)(base + (size_t)jj * PIX));
        float2 f0 = __half22float2(*(const __half2*)&u.x);
        float2 f1 = __half22float2(*(const __half2*)&u.y);
        acc.x += f0.x; acc.y += f0.y; acc.z += f1.x; acc.w += f1.y;
        const float ar = __ldg(alpha_ratio + j);
        const float ep = __ldg(epc + j);
        float4 o;
        o.x = fmaf(ar, xv.x, ep * acc.x);
        o.y = fmaf(ar, xv.y, ep * acc.y);
        o.z = fmaf(ar, xv.z, ep * acc.z);
        o.w = fmaf(ar, xv.w, ep * acc.w);
        ((float4*)dst)[(size_t)(j + 1) * PIX4 + p4] = o;
    }
}

extern "C" void kernel_launch(void* const* d_in, const int* in_sizes, int n_in,
                              void* d_out, int out_size)
{
    const float* x           = (const float*)d_in[0];  // (T+1, 3, 64, 64)
    const int*   t_arr       = (const int*)  d_in[1];  // (T,)
    const float* alpha_ratio = (const float*)d_in[2];  // (T,1,1,1)
    const float* et_coeff    = (const float*)d_in[3];  // (T,1,1,1)
    const float* epc         = (const float*)d_in[4];  // (T,1,1,1)
    const float* conv_w      = (const float*)d_in[5];  // (3,3,3,3)
    const float* temb        = (const float*)d_in[6];  // (T, 3)
    float*       out         = (float*)d_out;

    cudaMemcpyToSymbolAsync(c_w, conv_w, 81 * sizeof(float), 0,
                            cudaMemcpyDeviceToDevice);

    dim3 gA(H_DIM / TILE_ROWS, T_STEPS), bA(256);      // (4, 1000)
    dim3 gB(PIX4 / 256, NSEG),           bB(256);      // (12, 50)
    dim3 gP(PIX / 256),                  bP(256);      // (48)
    dim3 gC(PIX4 / 256, NSEG),           bC(256);      // (12, 50)

    for (int it = 0; it < 3; it++) {
        const float* src = (it == 0) ? x : out;  // conv reads images 0..T-1
        conv_kernel<<<gA, bA>>>(src, temb, t_arr, et_coeff);
        psum_kernel<<<gB, bB>>>();
        prefix_kernel<<<gP, bP>>>();
        scan_combine_kernel<<<gC, bC>>>(out, x, alpha_ratio, epc);
    }
}